// round 1
// baseline (speedup 1.0000x reference)
#include <cuda_runtime.h>
#include <math.h>

#define BATCH 4096
#define NIN   512
#define NREP  512
#define NOUT  640
#define RW    512
#define RB    64
#define NNZ   16384

// Scratch (static device allocations, allowed)
__device__ float g_t[RW];
__device__ float g_Wp[NOUT * NIN];
__device__ float g_bp[NOUT];
__device__ float g_lin[BATCH * NOUT];

// ---------------------------------------------------------------------------
// K0: zero the 512-float reduction target
// ---------------------------------------------------------------------------
__global__ void k_zero_t() {
    g_t[threadIdx.x] = 0.0f;
}

// ---------------------------------------------------------------------------
// K1: t = Qw^T @ wflat      (Qw: [327680, 512] row-major, streamed once)
// 1280 blocks x 512 threads; each block handles 256 rows, thread j owns col j.
// ---------------------------------------------------------------------------
__global__ __launch_bounds__(512) void k1_qwt(const float* __restrict__ Qw,
                                              const float* __restrict__ w) {
    __shared__ float s_w[256];
    const int tid = threadIdx.x;
    const int rowBase = blockIdx.x * 256;
    if (tid < 256) s_w[tid] = w[rowBase + tid];
    __syncthreads();

    float acc = 0.0f;
    const float* p = Qw + (size_t)rowBase * RW + tid;
#pragma unroll 8
    for (int i = 0; i < 256; i++) {
        acc += p[(size_t)i * RW] * s_w[i];
    }
    atomicAdd(&g_t[tid], acc);
}

// ---------------------------------------------------------------------------
// K1b: bp = Qb @ (Qb^T @ b)   (Qb: [640, 64])  -- tiny, one block
// ---------------------------------------------------------------------------
__global__ __launch_bounds__(640) void k_bias(const float* __restrict__ Qb,
                                              const float* __restrict__ b) {
    __shared__ float s_s[RB];
    const int tid = threadIdx.x;
    if (tid < RB) {
        float acc = 0.0f;
        for (int i = 0; i < NOUT; i++) acc += Qb[i * RB + tid] * b[i];
        s_s[tid] = acc;
    }
    __syncthreads();
    if (tid < NOUT) {
        float acc = 0.0f;
#pragma unroll
        for (int r = 0; r < RB; r++) acc += Qb[tid * RB + r] * s_s[r];
        g_bp[tid] = acc;
    }
}

// ---------------------------------------------------------------------------
// K2: Wp[i] = dot(Qw[i,:], t)   (second full stream of Qw)
// warp-per-row, float4 loads. 2560 blocks x 256 threads (8 warps),
// 16 rows per warp: 2560*8*16 = 327680 rows.
// ---------------------------------------------------------------------------
__global__ __launch_bounds__(256) void k2_wp(const float* __restrict__ Qw) {
    __shared__ float s_t[RW];
    const int tid = threadIdx.x;
    for (int i = tid; i < RW; i += 256) s_t[i] = g_t[i];
    __syncthreads();

    const int warp = tid >> 5;
    const int lane = tid & 31;
    const int row0 = (blockIdx.x * 8 + warp) * 16;
    const float4* t4 = reinterpret_cast<const float4*>(s_t);

    for (int rr = 0; rr < 16; rr++) {
        const int row = row0 + rr;
        const float4* p4 = reinterpret_cast<const float4*>(Qw + (size_t)row * RW);
        float acc = 0.0f;
#pragma unroll
        for (int u = 0; u < 4; u++) {
            float4 q = p4[lane + 32 * u];
            float4 tt = t4[lane + 32 * u];
            acc += q.x * tt.x + q.y * tt.y + q.z * tt.z + q.w * tt.w;
        }
#pragma unroll
        for (int off = 16; off > 0; off >>= 1)
            acc += __shfl_xor_sync(0xffffffffu, acc, off);
        if (lane == 0) g_Wp[row] = acc;
    }
}

// ---------------------------------------------------------------------------
// K3: lin = x @ Wp^T + bp     (4096x512 @ 512x640)
// SIMT tiled fp32 GEMM: BM=128, BN=64, BK=16, 256 threads, TM=8 x TN=4.
// ---------------------------------------------------------------------------
#define BM 128
#define BN 64
#define BK 16
#define TM 8
#define TN 4

__global__ __launch_bounds__(256) void k3_gemm(const float* __restrict__ x) {
    __shared__ float As[BK][BM];
    __shared__ float Bs[BK][BN];

    const int tid = threadIdx.x;
    const int tx = tid & 15;   // N direction
    const int ty = tid >> 4;   // M direction
    const int bn0 = blockIdx.x * BN;
    const int bm0 = blockIdx.y * BM;

    float acc[TM][TN];
#pragma unroll
    for (int i = 0; i < TM; i++)
#pragma unroll
        for (int j = 0; j < TN; j++) acc[i][j] = 0.0f;

    for (int k0 = 0; k0 < NIN; k0 += BK) {
        // load A tile: 128 rows x 16 cols = 512 float4, 2 per thread
#pragma unroll
        for (int i = 0; i < 2; i++) {
            const int idx = tid * 2 + i;
            const int m = idx >> 2;
            const int f4 = idx & 3;
            float4 v = *reinterpret_cast<const float4*>(
                x + (size_t)(bm0 + m) * NIN + k0 + f4 * 4);
            As[f4 * 4 + 0][m] = v.x;
            As[f4 * 4 + 1][m] = v.y;
            As[f4 * 4 + 2][m] = v.z;
            As[f4 * 4 + 3][m] = v.w;
        }
        // load B tile: 64 rows x 16 cols = 256 float4, 1 per thread
        {
            const int n = tid >> 2;
            const int f4 = tid & 3;
            float4 v = *reinterpret_cast<const float4*>(
                g_Wp + (size_t)(bn0 + n) * NIN + k0 + f4 * 4);
            Bs[f4 * 4 + 0][n] = v.x;
            Bs[f4 * 4 + 1][n] = v.y;
            Bs[f4 * 4 + 2][n] = v.z;
            Bs[f4 * 4 + 3][n] = v.w;
        }
        __syncthreads();

#pragma unroll
        for (int kk = 0; kk < BK; kk++) {
            float a[TM], bb[TN];
#pragma unroll
            for (int i = 0; i < TM; i++) a[i] = As[kk][ty * TM + i];
#pragma unroll
            for (int j = 0; j < TN; j++) bb[j] = Bs[kk][tx * TN + j];
#pragma unroll
            for (int i = 0; i < TM; i++)
#pragma unroll
                for (int j = 0; j < TN; j++) acc[i][j] += a[i] * bb[j];
        }
        __syncthreads();
    }

#pragma unroll
    for (int j = 0; j < TN; j++) {
        const int col = bn0 + tx * TN + j;
        const float bpv = g_bp[col];
#pragma unroll
        for (int i = 0; i < TM; i++) {
            const int row = bm0 + ty * TM + i;
            g_lin[(size_t)row * NOUT + col] = acc[i][j] + bpv;
        }
    }
}

// ---------------------------------------------------------------------------
// K4: bilinear scatter + preact + gated nonlinearity, one block per batch row
// ---------------------------------------------------------------------------
__global__ __launch_bounds__(256) void k4_bilinear_gate(
    const float* __restrict__ bi_params, const int* __restrict__ bi_src,
    const int* __restrict__ bi_row, const int* __restrict__ bi_col,
    const int* __restrict__ gate_idx, float* __restrict__ out) {
    __shared__ float s_lin[NOUT];
    __shared__ float s_acc[NOUT];

    const int b = blockIdx.x;
    const int tid = threadIdx.x;
    const float* lrow = g_lin + (size_t)b * NOUT;

    for (int j = tid; j < NOUT; j += 256) {
        s_lin[j] = lrow[j];
        s_acc[j] = 0.0f;
    }
    __syncthreads();

    for (int k = tid; k < NNZ; k += 256) {
        float v = bi_params[k] * s_lin[bi_src[k]] * s_lin[bi_col[k]];
        atomicAdd(&s_acc[bi_row[k]], v);
    }
    __syncthreads();

    for (int j = tid; j < NOUT; j += 256)
        s_acc[j] = 0.1f * s_acc[j] + s_lin[j];   // preact
    __syncthreads();

    for (int j = tid; j < NREP; j += 256) {
        float g = s_acc[gate_idx[j]];
        float sg = 1.0f / (1.0f + expf(-g));
        out[(size_t)b * NREP + j] = sg * s_acc[j];
    }
}

// ---------------------------------------------------------------------------
// Launch
// ---------------------------------------------------------------------------
extern "C" void kernel_launch(void* const* d_in, const int* in_sizes, int n_in,
                              void* d_out, int out_size) {
    const float* x        = (const float*)d_in[0];  // (4096, 512)
    const float* W_weight = (const float*)d_in[1];  // (640, 512)
    const float* b        = (const float*)d_in[2];  // (640,)
    const float* Qw       = (const float*)d_in[3];  // (327680, 512)
    const float* Qb       = (const float*)d_in[4];  // (640, 64)
    const float* bi_p     = (const float*)d_in[5];  // (16384,)
    const int*   bi_src   = (const int*)d_in[6];
    const int*   bi_row   = (const int*)d_in[7];
    const int*   bi_col   = (const int*)d_in[8];
    const int*   gate_idx = (const int*)d_in[9];
    float* out = (float*)d_out;                     // (4096, 512)

    k_zero_t<<<1, 512>>>();
    k1_qwt<<<1280, 512>>>(Qw, W_weight);
    k_bias<<<1, 640>>>(Qb, b);
    k2_wp<<<2560, 256>>>(Qw);
    k3_gemm<<<dim3(NOUT / BN, BATCH / BM), 256>>>(x);
    k4_bilinear_gate<<<BATCH, 256>>>(bi_p, bi_src, bi_row, bi_col, gate_idx, out);
}

// round 2
// speedup vs baseline: 1.0124x; 1.0124x over previous
#include <cuda_runtime.h>
#include <math.h>

#define BATCH 4096
#define NIN   512
#define NREP  512
#define NOUT  640
#define RW    512
#define RB    64
#define NNZ   16384

// Scratch (static device allocations, allowed)
__device__ float g_t[RW];
__device__ float g_Wp[NOUT * NIN];
__device__ float g_bp[NOUT];
__device__ float g_lin[BATCH * NOUT];
__device__ unsigned int g_packed[NNZ];

// ---------------------------------------------------------------------------
// K0: zero the 512-float reduction target
// ---------------------------------------------------------------------------
__global__ void k_zero_t() {
    g_t[threadIdx.x] = 0.0f;
}

// ---------------------------------------------------------------------------
// Kp: pack bilinear indices (src, col, row all < 1024) into one u32.
// Quarters the per-block index traffic in k4.
// ---------------------------------------------------------------------------
__global__ void k_pack(const int* __restrict__ src, const int* __restrict__ row,
                       const int* __restrict__ col) {
    const int k = blockIdx.x * 256 + threadIdx.x;
    g_packed[k] = (unsigned)src[k] | ((unsigned)col[k] << 10) |
                  ((unsigned)row[k] << 20);
}

// ---------------------------------------------------------------------------
// K1: t = Qw^T @ wflat      (Qw: [327680, 512] row-major, streamed once)
// 1280 blocks x 512 threads; each block handles 256 rows, thread j owns col j.
// (measured at DRAM roofline — keep)
// ---------------------------------------------------------------------------
__global__ __launch_bounds__(512) void k1_qwt(const float* __restrict__ Qw,
                                              const float* __restrict__ w) {
    __shared__ float s_w[256];
    const int tid = threadIdx.x;
    const int rowBase = blockIdx.x * 256;
    if (tid < 256) s_w[tid] = w[rowBase + tid];
    __syncthreads();

    float acc = 0.0f;
    const float* p = Qw + (size_t)rowBase * RW + tid;
#pragma unroll 8
    for (int i = 0; i < 256; i++) {
        acc += p[(size_t)i * RW] * s_w[i];
    }
    atomicAdd(&g_t[tid], acc);
}

// ---------------------------------------------------------------------------
// K1b: bp = Qb @ (Qb^T @ b)   (Qb: [640, 64])  -- tiny, one block
// ---------------------------------------------------------------------------
__global__ __launch_bounds__(640) void k_bias(const float* __restrict__ Qb,
                                              const float* __restrict__ b) {
    __shared__ float s_s[RB];
    const int tid = threadIdx.x;
    if (tid < RB) {
        float acc = 0.0f;
        for (int i = 0; i < NOUT; i++) acc += Qb[i * RB + tid] * b[i];
        s_s[tid] = acc;
    }
    __syncthreads();
    if (tid < NOUT) {
        float acc = 0.0f;
#pragma unroll
        for (int r = 0; r < RB; r++) acc += Qb[tid * RB + r] * s_s[r];
        g_bp[tid] = acc;
    }
}

// ---------------------------------------------------------------------------
// K2: Wp[i] = dot(Qw[i,:], t)   (second full stream of Qw) — at roofline, keep
// ---------------------------------------------------------------------------
__global__ __launch_bounds__(256) void k2_wp(const float* __restrict__ Qw) {
    __shared__ float s_t[RW];
    const int tid = threadIdx.x;
    for (int i = tid; i < RW; i += 256) s_t[i] = g_t[i];
    __syncthreads();

    const int warp = tid >> 5;
    const int lane = tid & 31;
    const int row0 = (blockIdx.x * 8 + warp) * 16;
    const float4* t4 = reinterpret_cast<const float4*>(s_t);

    for (int rr = 0; rr < 16; rr++) {
        const int row = row0 + rr;
        const float4* p4 = reinterpret_cast<const float4*>(Qw + (size_t)row * RW);
        float acc = 0.0f;
#pragma unroll
        for (int u = 0; u < 4; u++) {
            float4 q = p4[lane + 32 * u];
            float4 tt = t4[lane + 32 * u];
            acc += q.x * tt.x + q.y * tt.y + q.z * tt.z + q.w * tt.w;
        }
#pragma unroll
        for (int off = 16; off > 0; off >>= 1)
            acc += __shfl_xor_sync(0xffffffffu, acc, off);
        if (lane == 0) g_Wp[row] = acc;
    }
}

// ---------------------------------------------------------------------------
// K3: lin = x @ Wp^T + bp     (4096x512 @ 512x640)
// BM=BN=128, BK=16, 256 threads, 8x8 per-thread tile using packed
// fma.rn.f32x2 (Blackwell f32x2 pipe: 2x fp32 FMA throughput).
// grid = (640/128, 4096/128) = (5, 32) = 160 blocks, ~1 wave.
// ---------------------------------------------------------------------------
__global__ __launch_bounds__(256, 2) void k3_gemm(const float* __restrict__ x) {
    __shared__ float As[16][128];
    __shared__ float Bs[16][128];

    const int tid = threadIdx.x;
    const int tx = tid & 15;    // N direction (8 cols each)
    const int ty = tid >> 4;    // M direction (8 rows each)
    const int bn0 = blockIdx.x * 128;
    const int bm0 = blockIdx.y * 128;

    unsigned long long acc[8][4];   // 8 rows x 4 f32x2 pairs (=8 cols)
#pragma unroll
    for (int i = 0; i < 8; i++)
#pragma unroll
        for (int j = 0; j < 4; j++) acc[i][j] = 0ull;

    for (int k0 = 0; k0 < NIN; k0 += 16) {
        // A tile: 128 rows x 16 k = 512 float4, 2 per thread
#pragma unroll
        for (int i = 0; i < 2; i++) {
            const int idx = tid * 2 + i;
            const int m = idx >> 2;
            const int f4 = idx & 3;
            float4 v = *reinterpret_cast<const float4*>(
                x + (size_t)(bm0 + m) * NIN + k0 + f4 * 4);
            As[f4 * 4 + 0][m] = v.x;
            As[f4 * 4 + 1][m] = v.y;
            As[f4 * 4 + 2][m] = v.z;
            As[f4 * 4 + 3][m] = v.w;
        }
        // B tile: 128 n-rows x 16 k = 512 float4, 2 per thread
#pragma unroll
        for (int i = 0; i < 2; i++) {
            const int idx = tid * 2 + i;
            const int n = idx >> 2;
            const int f4 = idx & 3;
            float4 v = *reinterpret_cast<const float4*>(
                g_Wp + (size_t)(bn0 + n) * NIN + k0 + f4 * 4);
            Bs[f4 * 4 + 0][n] = v.x;
            Bs[f4 * 4 + 1][n] = v.y;
            Bs[f4 * 4 + 2][n] = v.z;
            Bs[f4 * 4 + 3][n] = v.w;
        }
        __syncthreads();

#pragma unroll
        for (int kk = 0; kk < 16; kk++) {
            unsigned long long a2[8];
#pragma unroll
            for (int i = 0; i < 8; i++) {
                float a = As[kk][ty * 8 + i];
                asm("mov.b64 %0, {%1, %1};" : "=l"(a2[i]) : "f"(a));
            }
            const unsigned long long* b2 =
                reinterpret_cast<const unsigned long long*>(&Bs[kk][tx * 8]);
            unsigned long long bb[4];
#pragma unroll
            for (int j = 0; j < 4; j++) bb[j] = b2[j];
#pragma unroll
            for (int i = 0; i < 8; i++)
#pragma unroll
                for (int j = 0; j < 4; j++)
                    asm("fma.rn.f32x2 %0, %1, %2, %0;"
                        : "+l"(acc[i][j]) : "l"(a2[i]), "l"(bb[j]));
        }
        __syncthreads();
    }

    // epilogue: unpack, add bias, store
#pragma unroll
    for (int j = 0; j < 4; j++) {
        const int col = bn0 + tx * 8 + j * 2;
        const float bp0 = g_bp[col];
        const float bp1 = g_bp[col + 1];
#pragma unroll
        for (int i = 0; i < 8; i++) {
            float lo, hi;
            asm("mov.b64 {%0, %1}, %2;" : "=f"(lo), "=f"(hi) : "l"(acc[i][j]));
            const int row = bm0 + ty * 8 + i;
            float2 v = make_float2(lo + bp0, hi + bp1);
            *reinterpret_cast<float2*>(g_lin + (size_t)row * NOUT + col) = v;
        }
    }
}

// ---------------------------------------------------------------------------
// K4: bilinear scatter + preact + gated nonlinearity.
// 4 batch rows per block (amortize index traffic 4x), packed indices (4x less).
// ---------------------------------------------------------------------------
#define K4_ROWS 4
#define K4_PAD  648   // 640 padded to break bank-conflict alignment across rows

__global__ __launch_bounds__(256) void k4_bilinear_gate(
    const float* __restrict__ bi_params, const int* __restrict__ gate_idx,
    float* __restrict__ out) {
    __shared__ float s_lin[K4_ROWS][K4_PAD];
    __shared__ float s_acc[K4_ROWS][K4_PAD];

    const int b0 = blockIdx.x * K4_ROWS;
    const int tid = threadIdx.x;

    for (int j = tid; j < NOUT; j += 256) {
#pragma unroll
        for (int r = 0; r < K4_ROWS; r++) {
            s_lin[r][j] = g_lin[(size_t)(b0 + r) * NOUT + j];
            s_acc[r][j] = 0.0f;
        }
    }
    __syncthreads();

    for (int k = tid; k < NNZ; k += 256) {
        const unsigned p = g_packed[k];
        const float w = bi_params[k];
        const int src = p & 1023;
        const int col = (p >> 10) & 1023;
        const int row = p >> 20;
#pragma unroll
        for (int r = 0; r < K4_ROWS; r++) {
            float v = w * s_lin[r][src] * s_lin[r][col];
            atomicAdd(&s_acc[r][row], v);
        }
    }
    __syncthreads();

    for (int j = tid; j < NOUT; j += 256) {
#pragma unroll
        for (int r = 0; r < K4_ROWS; r++)
            s_acc[r][j] = 0.1f * s_acc[r][j] + s_lin[r][j];   // preact
    }
    __syncthreads();

    for (int j = tid; j < NREP; j += 256) {
        const int gi = gate_idx[j];
#pragma unroll
        for (int r = 0; r < K4_ROWS; r++) {
            const float g = s_acc[r][gi];
            const float sg = 1.0f / (1.0f + __expf(-g));
            out[(size_t)(b0 + r) * NREP + j] = sg * s_acc[r][j];
        }
    }
}

// ---------------------------------------------------------------------------
// Launch
// ---------------------------------------------------------------------------
extern "C" void kernel_launch(void* const* d_in, const int* in_sizes, int n_in,
                              void* d_out, int out_size) {
    const float* x        = (const float*)d_in[0];  // (4096, 512)
    const float* W_weight = (const float*)d_in[1];  // (640, 512)
    const float* b        = (const float*)d_in[2];  // (640,)
    const float* Qw       = (const float*)d_in[3];  // (327680, 512)
    const float* Qb       = (const float*)d_in[4];  // (640, 64)
    const float* bi_p     = (const float*)d_in[5];  // (16384,)
    const int*   bi_src   = (const int*)d_in[6];
    const int*   bi_row   = (const int*)d_in[7];
    const int*   bi_col   = (const int*)d_in[8];
    const int*   gate_idx = (const int*)d_in[9];
    float* out = (float*)d_out;                     // (4096, 512)

    k_zero_t<<<1, 512>>>();
    k1_qwt<<<1280, 512>>>(Qw, W_weight);
    k_bias<<<1, 640>>>(Qb, b);
    k_pack<<<NNZ / 256, 256>>>(bi_src, bi_row, bi_col);
    k2_wp<<<2560, 256>>>(Qw);
    k3_gemm<<<dim3(NOUT / 128, BATCH / 128), 256>>>(x);
    k4_bilinear_gate<<<BATCH / K4_ROWS, 256>>>(bi_p, gate_idx, out);
}